// round 12
// baseline (speedup 1.0000x reference)
#include <cuda_runtime.h>

#define TSZ 16
#define SRR 4
#define PD 1
#define SSN 11          // 2*(SR+PADD)+1
#define WINSZ 26        // T + 2*(SR+PADD)
#define WINAREA (WINSZ*WINSZ)

// ---------------- scratch (no allocations allowed) ----------------
__device__ float g_ps1[4 * 256 * 256];
__device__ float g_pd1[4 * 256 * 256];
__device__ float g_ps2[4 * 128 * 128];
__device__ float g_pd2[4 * 128 * 128];
__device__ float g_ps3[4 * 64 * 64];
__device__ float g_pd3[4 * 64 * 64];
__device__ float g_off2[4 * 8 * 8 * 2];

// ---------------- fully fused pyramid with telescoped separable blur+pool ----------------
__global__ void __launch_bounds__(256) blur_all_kernel(
    const float* __restrict__ inS, const float* __restrict__ inD,
    float* __restrict__ o1S, float* __restrict__ o1D,
    float* __restrict__ o2S, float* __restrict__ o2D,
    float* __restrict__ o3S, float* __restrict__ o3D)
{
    __shared__ __align__(16) float A[92 * 92];   // l0, then l1 (stride 44), then l2 (stride 20)
    __shared__ float B[92 * 44];                 // hp, then hp2 (stride 20), then hp3 (stride 8)

    int bx = blockIdx.x, by = blockIdx.y, z = blockIdx.z;
    int tid = threadIdx.x;
    const float* in = (z < 4 ? inS : inD) + (size_t)(z & 3) * 512 * 512;
    float* o1 = (z < 4 ? o1S : o1D) + (size_t)(z & 3) * 256 * 256;
    float* o2 = (z < 4 ? o2S : o2D) + (size_t)(z & 3) * 128 * 128;
    float* o3 = (z < 4 ? o3S : o3D) + (size_t)(z & 3) * 64 * 64;

    const float w0 = 0.13533528323661270f;  // exp(-2)
    const float w1 = 0.60653065971263342f;  // exp(-0.5)
    const float ksum = 1.0f + 2.0f * w1 + 2.0f * w0;
    const float norm = 1.0f / (ksum * ksum);
    const float scale = 0.25f * norm;
    const float c6[6] = {w0, w0 + w1, 1.0f + w1, 1.0f + w1, w0 + w1, w0};

    // L0 halo: rows 64*by-14 .. +91, zero outside image (zero-pad conv semantics)
    int Y0 = 64 * by - 14, X0 = 64 * bx - 14;
    {
        int w = tid >> 5, lane = tid & 31;
        bool interior = (Y0 >= 0) && (Y0 + 92 <= 512) && (X0 >= 0) && (X0 + 92 <= 512);
        if (interior) {
            for (int r = w; r < 92; r += 8) {
                const float* src_row = in + (size_t)(Y0 + r) * 512 + X0;
                float* dst_row = A + r * 92;
                for (int c = lane; c < 92; c += 32)
                    dst_row[c] = src_row[c];
            }
        } else {
            for (int r = w; r < 92; r += 8) {
                int gy = Y0 + r;
                bool rowok = (gy >= 0 && gy < 512);
                const float* src_row = in + (size_t)max(gy, 0) * 512;
                float* dst_row = A + r * 92;
                for (int c = lane; c < 92; c += 32) {
                    int gx = X0 + c;
                    dst_row[c] = (rowok && gx >= 0 && gx < 512) ? src_row[gx] : 0.0f;
                }
            }
        }
    }
    __syncthreads();

    // hp: 92 rows x 22 column-pairs; thread = (y residue mod 11, pair p)
    if (tid < 242) {
        int y0h = tid / 22, p = tid - 22 * (tid / 22);
        for (int y = y0h; y < 92; y += 11) {
            const float4* q = (const float4*)(A + y * 92 + 4 * p);
            float4 v0 = q[0], v1 = q[1];
            float row[8] = {v0.x, v0.y, v0.z, v0.w, v1.x, v1.y, v1.z, v1.w};
            float s0 = 0.0f, s1 = 0.0f;
            #pragma unroll
            for (int j = 0; j < 6; j++) s0 = fmaf(c6[j], row[j], s0);
            #pragma unroll
            for (int j = 0; j < 6; j++) s1 = fmaf(c6[j], row[j + 2], s1);
            B[y * 44 + 2 * p] = s0;
            B[y * 44 + 2 * p + 1] = s1;
        }
    }
    __syncthreads();

    // L1 patch 44x44 (global L1 rows 32*by-6 .. +37), stored in A stride 44
    if (tid < 220) {
        int r0 = tid / 44, c = tid - 44 * (tid / 44);
        for (int r = r0; r < 44; r += 5) {
            int g1y = 32 * by - 6 + r, g1x = 32 * bx - 6 + c;
            float acc = 0.0f;
            if (g1y >= 0 && g1y < 256 && g1x >= 0 && g1x < 256) {
                float s = 0.0f;
                #pragma unroll
                for (int k = 0; k < 6; k++) s = fmaf(c6[k], B[(2 * r + k) * 44 + c], s);
                acc = s * scale;
            }
            A[r * 44 + c] = acc;
            if (r >= 6 && r < 38 && c >= 6 && c < 38)
                o1[(size_t)(32 * by + r - 6) * 256 + (32 * bx + c - 6)] = acc;
        }
    }
    __syncthreads();

    // hp2: 44 x 20
    if (tid < 220) {
        int y0h = tid / 20, c = tid - 20 * (tid / 20);
        for (int y = y0h; y < 44; y += 11) {
            const float* row = A + y * 44 + 2 * c;
            float s = 0.0f;
            #pragma unroll
            for (int j = 0; j < 6; j++) s = fmaf(c6[j], row[j], s);
            B[y * 20 + c] = s;
        }
    }
    __syncthreads();

    // L2 patch 20x20 (global L2 rows 16*by-2 .. +17), stored in A stride 20
    if (tid < 200) {
        int r0 = tid / 20, c = tid - 20 * (tid / 20);
        for (int r = r0; r < 20; r += 10) {
            int g2y = 16 * by - 2 + r, g2x = 16 * bx - 2 + c;
            float acc = 0.0f;
            if (g2y >= 0 && g2y < 128 && g2x >= 0 && g2x < 128) {
                float s = 0.0f;
                #pragma unroll
                for (int k = 0; k < 6; k++) s = fmaf(c6[k], B[(2 * r + k) * 20 + c], s);
                acc = s * scale;
            }
            A[r * 20 + c] = acc;
            if (r >= 2 && r < 18 && c >= 2 && c < 18)
                o2[(size_t)(16 * by + r - 2) * 128 + (16 * bx + c - 2)] = acc;
        }
    }
    __syncthreads();

    // hp3: 20 x 8
    if (tid < 160) {
        int y = tid >> 3, c = tid & 7;
        const float* row = A + y * 20 + 2 * c;
        float s = 0.0f;
        #pragma unroll
        for (int j = 0; j < 6; j++) s = fmaf(c6[j], row[j], s);
        B[y * 8 + c] = s;
    }
    __syncthreads();

    // L3 8x8
    if (tid < 64) {
        int t = tid >> 3, u = tid & 7;
        float s = 0.0f;
        #pragma unroll
        for (int k = 0; k < 6; k++) s = fmaf(c6[k], B[(2 * t + k) * 8 + u], s);
        o3[(size_t)(8 * by + t) * 64 + (8 * bx + u)] = s * scale;
    }
}

// ---------------- block matching ----------------
__device__ __forceinline__ void bar_sync_128(int id) {
    asm volatile("bar.sync %0, %1;" :: "r"(id), "r"(128) : "memory");
}
__device__ __forceinline__ unsigned long long u64min(unsigned long long a, unsigned long long b) {
    return a < b ? a : b;
}

// Subpixel refine from the winning key; computed redundantly by every thread
// (identical inputs/ops -> identical results, no publish barrier needed).
__device__ __forceinline__ void refine_calc(
    const float* sdist, float inity, float initx, unsigned long long key,
    float& offy, float& offx, float& best)
{
    int bk = (int)(key & 0xFFFFFFFFu);
    best = __uint_as_float((unsigned)(key >> 32));
    int py = bk / 9, px = bk - py * 9;
    offy = inity + (float)(py - SRR);
    offx = initx + (float)(px - SRR);

    int fy = py + 1, fx = px + 1;
    float y00 = sdist[(fy - 1) * SSN + fx - 1], y01 = sdist[(fy - 1) * SSN + fx], y02 = sdist[(fy - 1) * SSN + fx + 1];
    float y10 = sdist[fy * SSN + fx - 1],       y11 = sdist[fy * SSN + fx],       y12 = sdist[fy * SSN + fx + 1];
    float y20 = sdist[(fy + 1) * SSN + fx - 1], y21 = sdist[(fy + 1) * SSN + fx], y22 = sdist[(fy + 1) * SSN + fx + 1];

    float a11 = (y00 - 2.f * y01 + y02 + 2.f * y10 - 4.f * y11 + 2.f * y12 + y20 - 2.f * y21 + y22) * 0.25f;
    a11 = fmaxf(a11, 0.0f);
    float a22 = (y00 + 2.f * y01 + y02 - 2.f * y10 - 4.f * y11 - 2.f * y12 + y20 + 2.f * y21 + y22) * 0.25f;
    a22 = fmaxf(a22, 0.0f);
    float a12 = (y00 - y02 - y20 + y22) * 0.25f;
    float b1  = (-y00 + y02 - 2.f * y10 + 2.f * y12 - y20 + y22) * 0.125f;
    float b2  = (-y00 - 2.f * y01 - y02 + y20 + 2.f * y21 + y22) * 0.125f;

    float det = a11 * a22 - a12 * a12;
    float a12z = (det < 0.0f) ? 0.0f : a12;
    float mu_x = -(a22 * b1 - a12z * b2) / det;
    float mu_y = -(a11 * b2 - a12z * b1) / det;
    float mu_len = sqrtf(mu_y * mu_y + mu_x * mu_x);
    if (mu_len < 1.0f) { offx += mu_x; offy += mu_y; }  // false for NaN/inf, as in JAX
}

// Child tile match on a 128-thread group (gl=0..127, unique barId).
// Returns per-thread identical (offy, offx, best).
__device__ __forceinline__ void tile_match_child(
    int ty, int tx, float inity, float initx,
    const float* __restrict__ dbase, int H, int W,
    int gl, int barId, float* swin, const float* stile, float* sdist,
    unsigned long long* spart,
    float& offy, float& offx, float& best)
{
    int oy = (int)inity, ox = (int)initx;
    int y0 = ty * TSZ + oy - (SRR + PD);
    int x0 = tx * TSZ + ox - (SRR + PD);

    if (y0 >= 0 && y0 + WINSZ <= H && x0 >= 0 && x0 + WINSZ <= W) {
        const float* base = dbase + (size_t)y0 * W + x0;
        for (int i = gl; i < WINAREA; i += 128) {
            int wy = i / WINSZ, wx = i - wy * WINSZ;
            swin[i] = base[(size_t)wy * W + wx];
        }
    } else {
        for (int i = gl; i < WINAREA; i += 128) {
            int wy = i / WINSZ, wx = i - wy * WINSZ;
            int gy = min(max(y0 + wy, 0), H - 1);
            int gx = min(max(x0 + wx, 0), W - 1);
            swin[i] = dbase[(size_t)gy * W + gx];
        }
    }
    bar_sync_128(barId);

    if (gl < 96) {
        int cy = gl >> 3;
        int h = gl & 7;
        int cyc = (cy < SSN) ? cy : 0;

        float acc[SSN];
        #pragma unroll
        for (int c = 0; c < SSN; c++) acc[c] = 0.0f;

        #pragma unroll 1
        for (int rr = 0; rr < 2; rr++) {
            int yy = 2 * h + rr;
            const float* wr = swin + (cyc + yy) * WINSZ;
            float wreg[WINSZ];
            #pragma unroll
            for (int k = 0; k < WINSZ; k++) wreg[k] = wr[k];
            float treg[TSZ];
            const float4* t4 = (const float4*)(stile + yy * TSZ);
            #pragma unroll
            for (int q = 0; q < 4; q++) {
                float4 v = t4[q];
                treg[4 * q + 0] = v.x; treg[4 * q + 1] = v.y;
                treg[4 * q + 2] = v.z; treg[4 * q + 3] = v.w;
            }
            #pragma unroll
            for (int cx = 0; cx < SSN; cx++) {
                #pragma unroll
                for (int xx = 0; xx < TSZ; xx++) {
                    float d = wreg[cx + xx] - treg[xx];
                    acc[cx] = fmaf(d, d, acc[cx]);
                }
            }
        }
        #pragma unroll
        for (int c = 0; c < SSN; c++) {
            acc[c] += __shfl_down_sync(0xFFFFFFFFu, acc[c], 4);
            acc[c] += __shfl_down_sync(0xFFFFFFFFu, acc[c], 2);
            acc[c] += __shfl_down_sync(0xFFFFFFFFu, acc[c], 1);
        }
        if (h == 0 && cy < SSN) {
            float ay = (float)(cy - (SRR + PD)) / (float)SSN;
            #pragma unroll
            for (int cx = 0; cx < SSN; cx++) {
                float ax = (float)(cx - (SRR + PD)) / (float)SSN;
                sdist[cy * SSN + cx] = acc[cx] * (1.0f / 256.0f) + 0.1f * (ay * ay + ax * ax);
            }
        }
    }
    bar_sync_128(barId);

    // argmin partials (first-occurrence tie-break via index in low bits)
    unsigned long long key = 0xFFFFFFFFFFFFFFFFull;
    if (gl < 81) {
        int py = gl / 9, px = gl - py * 9;
        float v = sdist[(py + 1) * SSN + (px + 1)];
        key = ((unsigned long long)__float_as_uint(v) << 32) | (unsigned)gl;
    }
    if (gl < 96) {
        #pragma unroll
        for (int o = 16; o >= 1; o >>= 1)
            key = u64min(key, __shfl_down_sync(0xFFFFFFFFu, key, o));
        if ((gl & 31) == 0) spart[gl >> 5] = key;
    }
    bar_sync_128(barId);

    // every thread combines + refines redundantly (no publish barrier)
    key = u64min(u64min(spart[0], spart[1]), spart[2]);
    refine_calc(sdist, inity, initx, key, offy, offx, best);
}

// Fused two-level match: one CTA = one parent tile + its 4 child tiles.
__global__ void __launch_bounds__(512) match2_kernel(
    const float* __restrict__ srcP, const float* __restrict__ dstP, int Hp, int Wp,
    const float* __restrict__ srcC, const float* __restrict__ dstC, int Hc, int Wc,
    const float* __restrict__ grandOff, int ntwg,
    float* __restrict__ outChildOff, int ntwc,
    float* __restrict__ outPixOff, float* __restrict__ outPixDist)
{
    __shared__ float s_win[4][WINAREA];
    __shared__ __align__(16) float s_tile[4][TSZ * TSZ];
    __shared__ __align__(16) float s_ptile[TSZ * TSZ];
    __shared__ float s_dist[4][SSN * SSN];
    __shared__ float s_pdist[SSN * SSN];
    __shared__ unsigned long long s_part[4][3];
    __shared__ unsigned long long s_ppart[3];

    int tx = blockIdx.x, ty = blockIdx.y, n = blockIdx.z;
    int tid = threadIdx.x;
    const float* sPb = srcP + (size_t)n * Hp * Wp;
    const float* dPb = dstP + (size_t)n * Hp * Wp;
    const float* sCb = srcC + (size_t)n * Hc * Wc;
    const float* dCb = dstC + (size_t)n * Hc * Wc;

    // parent init offset: broadcast read, computed per-thread
    float inity = 0.0f, initx = 0.0f;
    if (grandOff) {
        const float* p = &grandOff[(((size_t)n * ntwg + (ty >> 1)) * ntwg + (tx >> 1)) * 2];
        float o0 = 2.0f * p[0], o1 = 2.0f * p[1];
        float fy = (float)(ty * TSZ), fx = (float)(tx * TSZ);
        inity = rintf(fminf(fmaxf(o0 + fy, 0.0f), (float)(Hp - TSZ)) - fy);
        initx = rintf(fminf(fmaxf(o1 + fx, 0.0f), (float)(Wp - TSZ)) - fx);
    }

    // ---- stage 0: all loads in parallel ----
    {
        int y0 = ty * TSZ + (int)inity - (SRR + PD);
        int x0 = tx * TSZ + (int)initx - (SRR + PD);
        if (y0 >= 0 && y0 + WINSZ <= Hp && x0 >= 0 && x0 + WINSZ <= Wp) {
            const float* base = dPb + (size_t)y0 * Wp + x0;
            for (int i = tid; i < WINAREA; i += 512) {
                int wy = i / WINSZ, wx = i - wy * WINSZ;
                s_win[0][i] = base[(size_t)wy * Wp + wx];
            }
        } else {
            for (int i = tid; i < WINAREA; i += 512) {
                int wy = i / WINSZ, wx = i - wy * WINSZ;
                int gy = min(max(y0 + wy, 0), Hp - 1);
                int gx = min(max(x0 + wx, 0), Wp - 1);
                s_win[0][i] = dPb[(size_t)gy * Wp + gx];
            }
        }
        if (tid < 256) {
            int yy = tid >> 4, xx = tid & 15;
            s_ptile[tid] = sPb[(size_t)(ty * TSZ + yy) * Wp + tx * TSZ + xx];
        }
        for (int i = tid; i < 4 * TSZ * TSZ; i += 512) {
            int child = i >> 8;
            int j = i & 255;
            int yy = j >> 4, xx = j & 15;
            int cty = 2 * ty + (child >> 1), ctx = 2 * tx + (child & 1);
            s_tile[child][j] = sCb[(size_t)(cty * TSZ + yy) * Wc + ctx * TSZ + xx];
        }
    }
    __syncthreads();

    // ---- stage 1: parent SSD across all 512 threads; warp w = candidate row cy ----
    {
        int cyp = tid >> 5;
        int h = tid & 31;
        if (cyp < SSN) {
            int row = h >> 1, half = h & 1;
            const float* wr = s_win[0] + (cyp + row) * WINSZ + half * 8;
            float wreg[18];
            #pragma unroll
            for (int k = 0; k < 18; k++) wreg[k] = wr[k];
            float treg[8];
            const float4* t4 = (const float4*)(s_ptile + row * TSZ + half * 8);
            float4 v0 = t4[0], v1 = t4[1];
            treg[0] = v0.x; treg[1] = v0.y; treg[2] = v0.z; treg[3] = v0.w;
            treg[4] = v1.x; treg[5] = v1.y; treg[6] = v1.z; treg[7] = v1.w;

            float acc[SSN];
            #pragma unroll
            for (int c = 0; c < SSN; c++) acc[c] = 0.0f;
            #pragma unroll
            for (int cx = 0; cx < SSN; cx++) {
                #pragma unroll
                for (int j = 0; j < 8; j++) {
                    float d = wreg[cx + j] - treg[j];
                    acc[cx] = fmaf(d, d, acc[cx]);
                }
            }
            #pragma unroll
            for (int c = 0; c < SSN; c++) {
                acc[c] += __shfl_down_sync(0xFFFFFFFFu, acc[c], 16);
                acc[c] += __shfl_down_sync(0xFFFFFFFFu, acc[c], 8);
                acc[c] += __shfl_down_sync(0xFFFFFFFFu, acc[c], 4);
                acc[c] += __shfl_down_sync(0xFFFFFFFFu, acc[c], 2);
                acc[c] += __shfl_down_sync(0xFFFFFFFFu, acc[c], 1);
            }
            if (h == 0) {
                float ay = (float)(cyp - (SRR + PD)) / (float)SSN;
                #pragma unroll
                for (int cx = 0; cx < SSN; cx++) {
                    float ax = (float)(cx - (SRR + PD)) / (float)SSN;
                    s_pdist[cyp * SSN + cx] = acc[cx] * (1.0f / 256.0f) + 0.1f * (ay * ay + ax * ax);
                }
            }
        }
    }
    __syncthreads();

    // parent argmin partials
    {
        unsigned long long key = 0xFFFFFFFFFFFFFFFFull;
        if (tid < 81) {
            int py = tid / 9, px = tid - py * 9;
            float v = s_pdist[(py + 1) * SSN + (px + 1)];
            key = ((unsigned long long)__float_as_uint(v) << 32) | (unsigned)tid;
        }
        if (tid < 96) {
            #pragma unroll
            for (int o = 16; o >= 1; o >>= 1)
                key = u64min(key, __shfl_down_sync(0xFFFFFFFFu, key, o));
            if ((tid & 31) == 0) s_ppart[tid >> 5] = key;
        }
    }
    __syncthreads();

    // all threads combine + refine parent redundantly (no publish barrier)
    float poy, pox, pbest;
    {
        unsigned long long key = u64min(u64min(s_ppart[0], s_ppart[1]), s_ppart[2]);
        refine_calc(s_pdist, inity, initx, key, poy, pox, pbest);
    }

    // ---- stage 2: 4 children in parallel ----
    int group = tid >> 7, gl = tid & 127;
    int cty = 2 * ty + (group >> 1), ctx = 2 * tx + (group & 1);
    float o0 = 2.0f * poy, o1 = 2.0f * pox;
    float fy = (float)(cty * TSZ), fx = (float)(ctx * TSZ);
    float ciy = rintf(fminf(fmaxf(o0 + fy, 0.0f), (float)(Hc - TSZ)) - fy);
    float cix = rintf(fminf(fmaxf(o1 + fx, 0.0f), (float)(Wc - TSZ)) - fx);

    float offy, offx, mind;
    tile_match_child(cty, ctx, ciy, cix, dCb, Hc, Wc,
                     gl, /*barId=*/1 + group, s_win[group], s_tile[group], s_dist[group],
                     s_part[group], offy, offx, mind);

    if (outChildOff) {
        if (gl == 0) {
            float* o = &outChildOff[(((size_t)n * ntwc + cty) * ntwc + ctx) * 2];
            o[0] = offy; o[1] = offx;
        }
    }
    if (outPixOff) {
        float2* po = (float2*)outPixOff;
        float2 ov = make_float2(offy, offx);
        for (int i = gl; i < TSZ * TSZ; i += 128) {
            int yy = i >> 4, xx = i & 15;
            size_t pidx = ((size_t)n * Hc + cty * TSZ + yy) * Wc + ctx * TSZ + xx;
            po[pidx] = ov;
            outPixDist[pidx] = mind;
        }
    }
}

extern "C" void kernel_launch(void* const* d_in, const int* in_sizes, int n_in,
                              void* d_out, int out_size) {
    (void)in_sizes; (void)n_in; (void)out_size;
    const float* src = (const float*)d_in[0];
    const float* dst = (const float*)d_in[1];

    float *ps1, *ps2, *ps3, *pd1, *pd2, *pd3, *off2;
    cudaGetSymbolAddress((void**)&ps1, g_ps1);
    cudaGetSymbolAddress((void**)&ps2, g_ps2);
    cudaGetSymbolAddress((void**)&ps3, g_ps3);
    cudaGetSymbolAddress((void**)&pd1, g_pd1);
    cudaGetSymbolAddress((void**)&pd2, g_pd2);
    cudaGetSymbolAddress((void**)&pd3, g_pd3);
    cudaGetSymbolAddress((void**)&off2, g_off2);

    float* outPixOff = (float*)d_out;                              // (4,512,512,2)
    float* outPixDist = (float*)d_out + (size_t)4 * 512 * 512 * 2; // (4,512,512)

    blur_all_kernel<<<dim3(8, 8, 8), 256>>>(src, dst, ps1, pd1, ps2, pd2, ps3, pd3);

    match2_kernel<<<dim3(4, 4, 4), 512>>>(ps3, pd3, 64, 64, ps2, pd2, 128, 128,
                                          nullptr, 0, off2, 8, nullptr, nullptr);
    match2_kernel<<<dim3(16, 16, 4), 512>>>(ps1, pd1, 256, 256, src, dst, 512, 512,
                                            off2, 8, nullptr, 0, outPixOff, outPixDist);
}

// round 15
// speedup vs baseline: 1.0319x; 1.0319x over previous
#include <cuda_runtime.h>

#define TSZ 16
#define SRR 4
#define PD 1
#define SSN 11          // 2*(SR+PADD)+1
#define WINSZ 26        // T + 2*(SR+PADD)
#define WINAREA (WINSZ*WINSZ)

// ---------------- scratch (no allocations allowed) ----------------
__device__ float g_ps1[4 * 256 * 256];
__device__ float g_pd1[4 * 256 * 256];
__device__ float g_ps2[4 * 128 * 128];
__device__ float g_pd2[4 * 128 * 128];
__device__ float g_ps3[4 * 64 * 64];
__device__ float g_pd3[4 * 64 * 64];
__device__ float g_off2[4 * 8 * 8 * 2];

// ---------------- fully fused pyramid with telescoped separable blur+pool ----------------
// (R9/R10 version -- measured 13.8us; flat i+=256 loops, float4 column pairs)
__global__ void __launch_bounds__(256) blur_all_kernel(
    const float* __restrict__ inS, const float* __restrict__ inD,
    float* __restrict__ o1S, float* __restrict__ o1D,
    float* __restrict__ o2S, float* __restrict__ o2D,
    float* __restrict__ o3S, float* __restrict__ o3D)
{
    __shared__ __align__(16) float A[92 * 92];   // l0, then l1 (stride 44), then l2 (stride 20)
    __shared__ float B[92 * 44];                 // hp, then hp2 (stride 20), then hp3 (stride 8)

    int bx = blockIdx.x, by = blockIdx.y, z = blockIdx.z;
    int tid = threadIdx.x;
    const float* in = (z < 4 ? inS : inD) + (size_t)(z & 3) * 512 * 512;
    float* o1 = (z < 4 ? o1S : o1D) + (size_t)(z & 3) * 256 * 256;
    float* o2 = (z < 4 ? o2S : o2D) + (size_t)(z & 3) * 128 * 128;
    float* o3 = (z < 4 ? o3S : o3D) + (size_t)(z & 3) * 64 * 64;

    const float w0 = 0.13533528323661270f;  // exp(-2)
    const float w1 = 0.60653065971263342f;  // exp(-0.5)
    const float ksum = 1.0f + 2.0f * w1 + 2.0f * w0;
    const float norm = 1.0f / (ksum * ksum);
    const float scale = 0.25f * norm;
    const float c6[6] = {w0, w0 + w1, 1.0f + w1, 1.0f + w1, w0 + w1, w0};

    int Y0 = 64 * by - 14, X0 = 64 * bx - 14;
    for (int i = tid; i < 92 * 92; i += 256) {
        int r = i / 92, c = i - r * 92;
        int gy = Y0 + r, gx = X0 + c;
        A[i] = (gy >= 0 && gy < 512 && gx >= 0 && gx < 512) ? in[(size_t)gy * 512 + gx] : 0.0f;
    }
    __syncthreads();

    for (int i = tid; i < 92 * 22; i += 256) {
        int y = i / 22, p = i - y * 22;
        const float4* q = (const float4*)(A + y * 92 + 4 * p);
        float4 v0 = q[0], v1 = q[1];
        float row[8] = {v0.x, v0.y, v0.z, v0.w, v1.x, v1.y, v1.z, v1.w};
        float s0 = 0.0f, s1 = 0.0f;
        #pragma unroll
        for (int j = 0; j < 6; j++) s0 = fmaf(c6[j], row[j], s0);
        #pragma unroll
        for (int j = 0; j < 6; j++) s1 = fmaf(c6[j], row[j + 2], s1);
        B[y * 44 + 2 * p] = s0;
        B[y * 44 + 2 * p + 1] = s1;
    }
    __syncthreads();

    for (int i = tid; i < 44 * 44; i += 256) {
        int r = i / 44, c = i - r * 44;
        int g1y = 32 * by - 6 + r, g1x = 32 * bx - 6 + c;
        float acc = 0.0f;
        if (g1y >= 0 && g1y < 256 && g1x >= 0 && g1x < 256) {
            float s = 0.0f;
            #pragma unroll
            for (int k = 0; k < 6; k++) s = fmaf(c6[k], B[(2 * r + k) * 44 + c], s);
            acc = s * scale;
        }
        A[i] = acc;
        if (r >= 6 && r < 38 && c >= 6 && c < 38)
            o1[(size_t)(32 * by + r - 6) * 256 + (32 * bx + c - 6)] = acc;
    }
    __syncthreads();

    for (int i = tid; i < 44 * 20; i += 256) {
        int y = i / 20, c = i - y * 20;
        const float* row = A + y * 44 + 2 * c;
        float s = 0.0f;
        #pragma unroll
        for (int j = 0; j < 6; j++) s = fmaf(c6[j], row[j], s);
        B[i] = s;
    }
    __syncthreads();

    for (int i = tid; i < 400; i += 256) {
        int r = i / 20, c = i - r * 20;
        int g2y = 16 * by - 2 + r, g2x = 16 * bx - 2 + c;
        float acc = 0.0f;
        if (g2y >= 0 && g2y < 128 && g2x >= 0 && g2x < 128) {
            float s = 0.0f;
            #pragma unroll
            for (int k = 0; k < 6; k++) s = fmaf(c6[k], B[(2 * r + k) * 20 + c], s);
            acc = s * scale;
        }
        A[i] = acc;
        if (r >= 2 && r < 18 && c >= 2 && c < 18)
            o2[(size_t)(16 * by + r - 2) * 128 + (16 * bx + c - 2)] = acc;
    }
    __syncthreads();

    if (tid < 160) {
        int y = tid >> 3, c = tid & 7;
        const float* row = A + y * 20 + 2 * c;
        float s = 0.0f;
        #pragma unroll
        for (int j = 0; j < 6; j++) s = fmaf(c6[j], row[j], s);
        B[y * 8 + c] = s;
    }
    __syncthreads();

    if (tid < 64) {
        int t = tid >> 3, u = tid & 7;
        float s = 0.0f;
        #pragma unroll
        for (int k = 0; k < 6; k++) s = fmaf(c6[k], B[(2 * t + k) * 8 + u], s);
        o3[(size_t)(8 * by + t) * 64 + (8 * bx + u)] = s * scale;
    }
}

// ---------------- block matching (R11 version -- measured best match side) ----------------
__device__ __forceinline__ void bar_sync_128(int id) {
    asm volatile("bar.sync %0, %1;" :: "r"(id), "r"(128) : "memory");
}
__device__ __forceinline__ unsigned long long u64min(unsigned long long a, unsigned long long b) {
    return a < b ? a : b;
}

// Subpixel refine from the winning key; computed redundantly by every thread
// (identical inputs/ops -> identical results, no publish barrier needed).
__device__ __forceinline__ void refine_calc(
    const float* sdist, float inity, float initx, unsigned long long key,
    float& offy, float& offx, float& best)
{
    int bk = (int)(key & 0xFFFFFFFFu);
    best = __uint_as_float((unsigned)(key >> 32));
    int py = bk / 9, px = bk - py * 9;
    offy = inity + (float)(py - SRR);
    offx = initx + (float)(px - SRR);

    int fy = py + 1, fx = px + 1;
    float y00 = sdist[(fy - 1) * SSN + fx - 1], y01 = sdist[(fy - 1) * SSN + fx], y02 = sdist[(fy - 1) * SSN + fx + 1];
    float y10 = sdist[fy * SSN + fx - 1],       y11 = sdist[fy * SSN + fx],       y12 = sdist[fy * SSN + fx + 1];
    float y20 = sdist[(fy + 1) * SSN + fx - 1], y21 = sdist[(fy + 1) * SSN + fx], y22 = sdist[(fy + 1) * SSN + fx + 1];

    float a11 = (y00 - 2.f * y01 + y02 + 2.f * y10 - 4.f * y11 + 2.f * y12 + y20 - 2.f * y21 + y22) * 0.25f;
    a11 = fmaxf(a11, 0.0f);
    float a22 = (y00 + 2.f * y01 + y02 - 2.f * y10 - 4.f * y11 - 2.f * y12 + y20 + 2.f * y21 + y22) * 0.25f;
    a22 = fmaxf(a22, 0.0f);
    float a12 = (y00 - y02 - y20 + y22) * 0.25f;
    float b1  = (-y00 + y02 - 2.f * y10 + 2.f * y12 - y20 + y22) * 0.125f;
    float b2  = (-y00 - 2.f * y01 - y02 + y20 + 2.f * y21 + y22) * 0.125f;

    float det = a11 * a22 - a12 * a12;
    float a12z = (det < 0.0f) ? 0.0f : a12;
    float mu_x = -(a22 * b1 - a12z * b2) / det;
    float mu_y = -(a11 * b2 - a12z * b1) / det;
    float mu_len = sqrtf(mu_y * mu_y + mu_x * mu_x);
    if (mu_len < 1.0f) { offx += mu_x; offy += mu_y; }  // false for NaN/inf, as in JAX
}

// Child tile match on a 128-thread group (gl=0..127, unique barId).
__device__ __forceinline__ void tile_match_child(
    int ty, int tx, float inity, float initx,
    const float* __restrict__ dbase, int H, int W,
    int gl, int barId, float* swin, const float* stile, float* sdist,
    unsigned long long* spart,
    float& offy, float& offx, float& best)
{
    int oy = (int)inity, ox = (int)initx;
    int y0 = ty * TSZ + oy - (SRR + PD);
    int x0 = tx * TSZ + ox - (SRR + PD);

    if (y0 >= 0 && y0 + WINSZ <= H && x0 >= 0 && x0 + WINSZ <= W) {
        const float* base = dbase + (size_t)y0 * W + x0;
        for (int i = gl; i < WINAREA; i += 128) {
            int wy = i / WINSZ, wx = i - wy * WINSZ;
            swin[i] = base[(size_t)wy * W + wx];
        }
    } else {
        for (int i = gl; i < WINAREA; i += 128) {
            int wy = i / WINSZ, wx = i - wy * WINSZ;
            int gy = min(max(y0 + wy, 0), H - 1);
            int gx = min(max(x0 + wx, 0), W - 1);
            swin[i] = dbase[(size_t)gy * W + gx];
        }
    }
    bar_sync_128(barId);

    if (gl < 96) {
        int cy = gl >> 3;
        int h = gl & 7;
        int cyc = (cy < SSN) ? cy : 0;

        float acc[SSN];
        #pragma unroll
        for (int c = 0; c < SSN; c++) acc[c] = 0.0f;

        #pragma unroll 1
        for (int rr = 0; rr < 2; rr++) {
            int yy = 2 * h + rr;
            const float* wr = swin + (cyc + yy) * WINSZ;
            float wreg[WINSZ];
            #pragma unroll
            for (int k = 0; k < WINSZ; k++) wreg[k] = wr[k];
            float treg[TSZ];
            const float4* t4 = (const float4*)(stile + yy * TSZ);
            #pragma unroll
            for (int q = 0; q < 4; q++) {
                float4 v = t4[q];
                treg[4 * q + 0] = v.x; treg[4 * q + 1] = v.y;
                treg[4 * q + 2] = v.z; treg[4 * q + 3] = v.w;
            }
            #pragma unroll
            for (int cx = 0; cx < SSN; cx++) {
                #pragma unroll
                for (int xx = 0; xx < TSZ; xx++) {
                    float d = wreg[cx + xx] - treg[xx];
                    acc[cx] = fmaf(d, d, acc[cx]);
                }
            }
        }
        #pragma unroll
        for (int c = 0; c < SSN; c++) {
            acc[c] += __shfl_down_sync(0xFFFFFFFFu, acc[c], 4);
            acc[c] += __shfl_down_sync(0xFFFFFFFFu, acc[c], 2);
            acc[c] += __shfl_down_sync(0xFFFFFFFFu, acc[c], 1);
        }
        if (h == 0 && cy < SSN) {
            float ay = (float)(cy - (SRR + PD)) / (float)SSN;
            #pragma unroll
            for (int cx = 0; cx < SSN; cx++) {
                float ax = (float)(cx - (SRR + PD)) / (float)SSN;
                sdist[cy * SSN + cx] = acc[cx] * (1.0f / 256.0f) + 0.1f * (ay * ay + ax * ax);
            }
        }
    }
    bar_sync_128(barId);

    // argmin partials (first-occurrence tie-break via index in low bits)
    unsigned long long key = 0xFFFFFFFFFFFFFFFFull;
    if (gl < 81) {
        int py = gl / 9, px = gl - py * 9;
        float v = sdist[(py + 1) * SSN + (px + 1)];
        key = ((unsigned long long)__float_as_uint(v) << 32) | (unsigned)gl;
    }
    if (gl < 96) {
        #pragma unroll
        for (int o = 16; o >= 1; o >>= 1)
            key = u64min(key, __shfl_down_sync(0xFFFFFFFFu, key, o));
        if ((gl & 31) == 0) spart[gl >> 5] = key;
    }
    bar_sync_128(barId);

    // every thread combines + refines redundantly (no publish barrier)
    key = u64min(u64min(spart[0], spart[1]), spart[2]);
    refine_calc(sdist, inity, initx, key, offy, offx, best);
}

// Fused two-level match: one CTA = one parent tile + its 4 child tiles.
__global__ void __launch_bounds__(512) match2_kernel(
    const float* __restrict__ srcP, const float* __restrict__ dstP, int Hp, int Wp,
    const float* __restrict__ srcC, const float* __restrict__ dstC, int Hc, int Wc,
    const float* __restrict__ grandOff, int ntwg,
    float* __restrict__ outChildOff, int ntwc,
    float* __restrict__ outPixOff, float* __restrict__ outPixDist)
{
    __shared__ float s_win[4][WINAREA];
    __shared__ __align__(16) float s_tile[4][TSZ * TSZ];
    __shared__ __align__(16) float s_ptile[TSZ * TSZ];
    __shared__ float s_dist[4][SSN * SSN];
    __shared__ float s_pdist[SSN * SSN];
    __shared__ unsigned long long s_part[4][3];
    __shared__ unsigned long long s_ppart[3];

    int tx = blockIdx.x, ty = blockIdx.y, n = blockIdx.z;
    int tid = threadIdx.x;
    const float* sPb = srcP + (size_t)n * Hp * Wp;
    const float* dPb = dstP + (size_t)n * Hp * Wp;
    const float* sCb = srcC + (size_t)n * Hc * Wc;
    const float* dCb = dstC + (size_t)n * Hc * Wc;

    // parent init offset: broadcast read, computed per-thread
    float inity = 0.0f, initx = 0.0f;
    if (grandOff) {
        const float* p = &grandOff[(((size_t)n * ntwg + (ty >> 1)) * ntwg + (tx >> 1)) * 2];
        float o0 = 2.0f * p[0], o1 = 2.0f * p[1];
        float fy = (float)(ty * TSZ), fx = (float)(tx * TSZ);
        inity = rintf(fminf(fmaxf(o0 + fy, 0.0f), (float)(Hp - TSZ)) - fy);
        initx = rintf(fminf(fmaxf(o1 + fx, 0.0f), (float)(Wp - TSZ)) - fx);
    }

    // ---- stage 0: all loads in parallel ----
    {
        int y0 = ty * TSZ + (int)inity - (SRR + PD);
        int x0 = tx * TSZ + (int)initx - (SRR + PD);
        if (y0 >= 0 && y0 + WINSZ <= Hp && x0 >= 0 && x0 + WINSZ <= Wp) {
            const float* base = dPb + (size_t)y0 * Wp + x0;
            for (int i = tid; i < WINAREA; i += 512) {
                int wy = i / WINSZ, wx = i - wy * WINSZ;
                s_win[0][i] = base[(size_t)wy * Wp + wx];
            }
        } else {
            for (int i = tid; i < WINAREA; i += 512) {
                int wy = i / WINSZ, wx = i - wy * WINSZ;
                int gy = min(max(y0 + wy, 0), Hp - 1);
                int gx = min(max(x0 + wx, 0), Wp - 1);
                s_win[0][i] = dPb[(size_t)gy * Wp + gx];
            }
        }
        if (tid < 256) {
            int yy = tid >> 4, xx = tid & 15;
            s_ptile[tid] = sPb[(size_t)(ty * TSZ + yy) * Wp + tx * TSZ + xx];
        }
        for (int i = tid; i < 4 * TSZ * TSZ; i += 512) {
            int child = i >> 8;
            int j = i & 255;
            int yy = j >> 4, xx = j & 15;
            int cty = 2 * ty + (child >> 1), ctx = 2 * tx + (child & 1);
            s_tile[child][j] = sCb[(size_t)(cty * TSZ + yy) * Wc + ctx * TSZ + xx];
        }
    }
    __syncthreads();

    // ---- stage 1: parent SSD across all 512 threads; warp w = candidate row cy ----
    {
        int cyp = tid >> 5;
        int h = tid & 31;
        if (cyp < SSN) {
            int row = h >> 1, half = h & 1;
            const float* wr = s_win[0] + (cyp + row) * WINSZ + half * 8;
            float wreg[18];
            #pragma unroll
            for (int k = 0; k < 18; k++) wreg[k] = wr[k];
            float treg[8];
            const float4* t4 = (const float4*)(s_ptile + row * TSZ + half * 8);
            float4 v0 = t4[0], v1 = t4[1];
            treg[0] = v0.x; treg[1] = v0.y; treg[2] = v0.z; treg[3] = v0.w;
            treg[4] = v1.x; treg[5] = v1.y; treg[6] = v1.z; treg[7] = v1.w;

            float acc[SSN];
            #pragma unroll
            for (int c = 0; c < SSN; c++) acc[c] = 0.0f;
            #pragma unroll
            for (int cx = 0; cx < SSN; cx++) {
                #pragma unroll
                for (int j = 0; j < 8; j++) {
                    float d = wreg[cx + j] - treg[j];
                    acc[cx] = fmaf(d, d, acc[cx]);
                }
            }
            #pragma unroll
            for (int c = 0; c < SSN; c++) {
                acc[c] += __shfl_down_sync(0xFFFFFFFFu, acc[c], 16);
                acc[c] += __shfl_down_sync(0xFFFFFFFFu, acc[c], 8);
                acc[c] += __shfl_down_sync(0xFFFFFFFFu, acc[c], 4);
                acc[c] += __shfl_down_sync(0xFFFFFFFFu, acc[c], 2);
                acc[c] += __shfl_down_sync(0xFFFFFFFFu, acc[c], 1);
            }
            if (h == 0) {
                float ay = (float)(cyp - (SRR + PD)) / (float)SSN;
                #pragma unroll
                for (int cx = 0; cx < SSN; cx++) {
                    float ax = (float)(cx - (SRR + PD)) / (float)SSN;
                    s_pdist[cyp * SSN + cx] = acc[cx] * (1.0f / 256.0f) + 0.1f * (ay * ay + ax * ax);
                }
            }
        }
    }
    __syncthreads();

    // parent argmin partials
    {
        unsigned long long key = 0xFFFFFFFFFFFFFFFFull;
        if (tid < 81) {
            int py = tid / 9, px = tid - py * 9;
            float v = s_pdist[(py + 1) * SSN + (px + 1)];
            key = ((unsigned long long)__float_as_uint(v) << 32) | (unsigned)tid;
        }
        if (tid < 96) {
            #pragma unroll
            for (int o = 16; o >= 1; o >>= 1)
                key = u64min(key, __shfl_down_sync(0xFFFFFFFFu, key, o));
            if ((tid & 31) == 0) s_ppart[tid >> 5] = key;
        }
    }
    __syncthreads();

    // all threads combine + refine parent redundantly (no publish barrier)
    float poy, pox, pbest;
    {
        unsigned long long key = u64min(u64min(s_ppart[0], s_ppart[1]), s_ppart[2]);
        refine_calc(s_pdist, inity, initx, key, poy, pox, pbest);
    }

    // ---- stage 2: 4 children in parallel ----
    int group = tid >> 7, gl = tid & 127;
    int cty = 2 * ty + (group >> 1), ctx = 2 * tx + (group & 1);
    float o0 = 2.0f * poy, o1 = 2.0f * pox;
    float fy = (float)(cty * TSZ), fx = (float)(ctx * TSZ);
    float ciy = rintf(fminf(fmaxf(o0 + fy, 0.0f), (float)(Hc - TSZ)) - fy);
    float cix = rintf(fminf(fmaxf(o1 + fx, 0.0f), (float)(Wc - TSZ)) - fx);

    float offy, offx, mind;
    tile_match_child(cty, ctx, ciy, cix, dCb, Hc, Wc,
                     gl, /*barId=*/1 + group, s_win[group], s_tile[group], s_dist[group],
                     s_part[group], offy, offx, mind);

    if (outChildOff) {
        if (gl == 0) {
            float* o = &outChildOff[(((size_t)n * ntwc + cty) * ntwc + ctx) * 2];
            o[0] = offy; o[1] = offx;
        }
    }
    if (outPixOff) {
        float2* po = (float2*)outPixOff;
        float2 ov = make_float2(offy, offx);
        for (int i = gl; i < TSZ * TSZ; i += 128) {
            int yy = i >> 4, xx = i & 15;
            size_t pidx = ((size_t)n * Hc + cty * TSZ + yy) * Wc + ctx * TSZ + xx;
            po[pidx] = ov;
            outPixDist[pidx] = mind;
        }
    }
}

extern "C" void kernel_launch(void* const* d_in, const int* in_sizes, int n_in,
                              void* d_out, int out_size) {
    (void)in_sizes; (void)n_in; (void)out_size;
    const float* src = (const float*)d_in[0];
    const float* dst = (const float*)d_in[1];

    float *ps1, *ps2, *ps3, *pd1, *pd2, *pd3, *off2;
    cudaGetSymbolAddress((void**)&ps1, g_ps1);
    cudaGetSymbolAddress((void**)&ps2, g_ps2);
    cudaGetSymbolAddress((void**)&ps3, g_ps3);
    cudaGetSymbolAddress((void**)&pd1, g_pd1);
    cudaGetSymbolAddress((void**)&pd2, g_pd2);
    cudaGetSymbolAddress((void**)&pd3, g_pd3);
    cudaGetSymbolAddress((void**)&off2, g_off2);

    float* outPixOff = (float*)d_out;                              // (4,512,512,2)
    float* outPixDist = (float*)d_out + (size_t)4 * 512 * 512 * 2; // (4,512,512)

    blur_all_kernel<<<dim3(8, 8, 8), 256>>>(src, dst, ps1, pd1, ps2, pd2, ps3, pd3);

    match2_kernel<<<dim3(4, 4, 4), 512>>>(ps3, pd3, 64, 64, ps2, pd2, 128, 128,
                                          nullptr, 0, off2, 8, nullptr, nullptr);
    match2_kernel<<<dim3(16, 16, 4), 512>>>(ps1, pd1, 256, 256, src, dst, 512, 512,
                                            off2, 8, nullptr, 0, outPixOff, outPixDist);
}

// round 16
// speedup vs baseline: 1.0659x; 1.0329x over previous
#include <cuda_runtime.h>

#define TSZ 16
#define SRR 4
#define PD 1
#define SSN 11          // 2*(SR+PADD)+1
#define WINSZ 26        // T + 2*(SR+PADD)
#define WINAREA (WINSZ*WINSZ)

// ---------------- scratch (no allocations allowed) ----------------
__device__ float g_ps1[4 * 256 * 256];
__device__ float g_pd1[4 * 256 * 256];
__device__ float g_ps2[4 * 128 * 128];
__device__ float g_pd2[4 * 128 * 128];
__device__ float g_ps3[4 * 64 * 64];
__device__ float g_pd3[4 * 64 * 64];
__device__ float g_off2[4 * 8 * 8 * 2];

// ---------------- fully fused pyramid with telescoped separable blur+pool ----------------
// (measured 13.6us; flat i+=256 loops, float4 column pairs)
__global__ void __launch_bounds__(256) blur_all_kernel(
    const float* __restrict__ inS, const float* __restrict__ inD,
    float* __restrict__ o1S, float* __restrict__ o1D,
    float* __restrict__ o2S, float* __restrict__ o2D,
    float* __restrict__ o3S, float* __restrict__ o3D)
{
    __shared__ __align__(16) float A[92 * 92];   // l0, then l1 (stride 44), then l2 (stride 20)
    __shared__ float B[92 * 44];                 // hp, then hp2 (stride 20), then hp3 (stride 8)

    int bx = blockIdx.x, by = blockIdx.y, z = blockIdx.z;
    int tid = threadIdx.x;
    const float* in = (z < 4 ? inS : inD) + (size_t)(z & 3) * 512 * 512;
    float* o1 = (z < 4 ? o1S : o1D) + (size_t)(z & 3) * 256 * 256;
    float* o2 = (z < 4 ? o2S : o2D) + (size_t)(z & 3) * 128 * 128;
    float* o3 = (z < 4 ? o3S : o3D) + (size_t)(z & 3) * 64 * 64;

    const float w0 = 0.13533528323661270f;  // exp(-2)
    const float w1 = 0.60653065971263342f;  // exp(-0.5)
    const float ksum = 1.0f + 2.0f * w1 + 2.0f * w0;
    const float norm = 1.0f / (ksum * ksum);
    const float scale = 0.25f * norm;
    const float c6[6] = {w0, w0 + w1, 1.0f + w1, 1.0f + w1, w0 + w1, w0};

    int Y0 = 64 * by - 14, X0 = 64 * bx - 14;
    for (int i = tid; i < 92 * 92; i += 256) {
        int r = i / 92, c = i - r * 92;
        int gy = Y0 + r, gx = X0 + c;
        A[i] = (gy >= 0 && gy < 512 && gx >= 0 && gx < 512) ? in[(size_t)gy * 512 + gx] : 0.0f;
    }
    __syncthreads();

    for (int i = tid; i < 92 * 22; i += 256) {
        int y = i / 22, p = i - y * 22;
        const float4* q = (const float4*)(A + y * 92 + 4 * p);
        float4 v0 = q[0], v1 = q[1];
        float row[8] = {v0.x, v0.y, v0.z, v0.w, v1.x, v1.y, v1.z, v1.w};
        float s0 = 0.0f, s1 = 0.0f;
        #pragma unroll
        for (int j = 0; j < 6; j++) s0 = fmaf(c6[j], row[j], s0);
        #pragma unroll
        for (int j = 0; j < 6; j++) s1 = fmaf(c6[j], row[j + 2], s1);
        B[y * 44 + 2 * p] = s0;
        B[y * 44 + 2 * p + 1] = s1;
    }
    __syncthreads();

    for (int i = tid; i < 44 * 44; i += 256) {
        int r = i / 44, c = i - r * 44;
        int g1y = 32 * by - 6 + r, g1x = 32 * bx - 6 + c;
        float acc = 0.0f;
        if (g1y >= 0 && g1y < 256 && g1x >= 0 && g1x < 256) {
            float s = 0.0f;
            #pragma unroll
            for (int k = 0; k < 6; k++) s = fmaf(c6[k], B[(2 * r + k) * 44 + c], s);
            acc = s * scale;
        }
        A[i] = acc;
        if (r >= 6 && r < 38 && c >= 6 && c < 38)
            o1[(size_t)(32 * by + r - 6) * 256 + (32 * bx + c - 6)] = acc;
    }
    __syncthreads();

    for (int i = tid; i < 44 * 20; i += 256) {
        int y = i / 20, c = i - y * 20;
        const float* row = A + y * 44 + 2 * c;
        float s = 0.0f;
        #pragma unroll
        for (int j = 0; j < 6; j++) s = fmaf(c6[j], row[j], s);
        B[i] = s;
    }
    __syncthreads();

    for (int i = tid; i < 400; i += 256) {
        int r = i / 20, c = i - r * 20;
        int g2y = 16 * by - 2 + r, g2x = 16 * bx - 2 + c;
        float acc = 0.0f;
        if (g2y >= 0 && g2y < 128 && g2x >= 0 && g2x < 128) {
            float s = 0.0f;
            #pragma unroll
            for (int k = 0; k < 6; k++) s = fmaf(c6[k], B[(2 * r + k) * 20 + c], s);
            acc = s * scale;
        }
        A[i] = acc;
        if (r >= 2 && r < 18 && c >= 2 && c < 18)
            o2[(size_t)(16 * by + r - 2) * 128 + (16 * bx + c - 2)] = acc;
    }
    __syncthreads();

    if (tid < 160) {
        int y = tid >> 3, c = tid & 7;
        const float* row = A + y * 20 + 2 * c;
        float s = 0.0f;
        #pragma unroll
        for (int j = 0; j < 6; j++) s = fmaf(c6[j], row[j], s);
        B[y * 8 + c] = s;
    }
    __syncthreads();

    if (tid < 64) {
        int t = tid >> 3, u = tid & 7;
        float s = 0.0f;
        #pragma unroll
        for (int k = 0; k < 6; k++) s = fmaf(c6[k], B[(2 * t + k) * 8 + u], s);
        o3[(size_t)(8 * by + t) * 64 + (8 * bx + u)] = s * scale;
    }
}

// ---------------- block matching ----------------
__device__ __forceinline__ void bar_sync_128(int id) {
    asm volatile("bar.sync %0, %1;" :: "r"(id), "r"(128) : "memory");
}
__device__ __forceinline__ unsigned long long u64min(unsigned long long a, unsigned long long b) {
    return a < b ? a : b;
}

// Subpixel refine from the winning key; computed redundantly by every thread
// (identical inputs/ops -> identical results, no publish barrier needed).
__device__ __forceinline__ void refine_calc(
    const float* sdist, float inity, float initx, unsigned long long key,
    float& offy, float& offx, float& best)
{
    int bk = (int)(key & 0xFFFFFFFFu);
    best = __uint_as_float((unsigned)(key >> 32));
    int py = bk / 9, px = bk - py * 9;
    offy = inity + (float)(py - SRR);
    offx = initx + (float)(px - SRR);

    int fy = py + 1, fx = px + 1;
    float y00 = sdist[(fy - 1) * SSN + fx - 1], y01 = sdist[(fy - 1) * SSN + fx], y02 = sdist[(fy - 1) * SSN + fx + 1];
    float y10 = sdist[fy * SSN + fx - 1],       y11 = sdist[fy * SSN + fx],       y12 = sdist[fy * SSN + fx + 1];
    float y20 = sdist[(fy + 1) * SSN + fx - 1], y21 = sdist[(fy + 1) * SSN + fx], y22 = sdist[(fy + 1) * SSN + fx + 1];

    float a11 = (y00 - 2.f * y01 + y02 + 2.f * y10 - 4.f * y11 + 2.f * y12 + y20 - 2.f * y21 + y22) * 0.25f;
    a11 = fmaxf(a11, 0.0f);
    float a22 = (y00 + 2.f * y01 + y02 - 2.f * y10 - 4.f * y11 - 2.f * y12 + y20 + 2.f * y21 + y22) * 0.25f;
    a22 = fmaxf(a22, 0.0f);
    float a12 = (y00 - y02 - y20 + y22) * 0.25f;
    float b1  = (-y00 + y02 - 2.f * y10 + 2.f * y12 - y20 + y22) * 0.125f;
    float b2  = (-y00 - 2.f * y01 - y02 + y20 + 2.f * y21 + y22) * 0.125f;

    float det = a11 * a22 - a12 * a12;
    float a12z = (det < 0.0f) ? 0.0f : a12;
    float mu_x = -(a22 * b1 - a12z * b2) / det;
    float mu_y = -(a11 * b2 - a12z * b1) / det;
    float mu_len = sqrtf(mu_y * mu_y + mu_x * mu_x);
    if (mu_len < 1.0f) { offx += mu_x; offy += mu_y; }  // false for NaN/inf, as in JAX
}

// Child tile match on a 128-thread group (gl=0..127, unique barId).
// SSD processes each row in two 8-element halves: per-accumulator op order is
// xx=0..7 then xx=8..15 -- identical to the previous xx=0..15 order, so sums
// are bit-identical while live registers drop from ~53 to ~37.
__device__ __forceinline__ void tile_match_child(
    int ty, int tx, float inity, float initx,
    const float* __restrict__ dbase, int H, int W,
    int gl, int barId, float* swin, const float* stile, float* sdist,
    unsigned long long* spart,
    float& offy, float& offx, float& best)
{
    int oy = (int)inity, ox = (int)initx;
    int y0 = ty * TSZ + oy - (SRR + PD);
    int x0 = tx * TSZ + ox - (SRR + PD);

    if (y0 >= 0 && y0 + WINSZ <= H && x0 >= 0 && x0 + WINSZ <= W) {
        const float* base = dbase + (size_t)y0 * W + x0;
        for (int i = gl; i < WINAREA; i += 128) {
            int wy = i / WINSZ, wx = i - wy * WINSZ;
            swin[i] = base[(size_t)wy * W + wx];
        }
    } else {
        for (int i = gl; i < WINAREA; i += 128) {
            int wy = i / WINSZ, wx = i - wy * WINSZ;
            int gy = min(max(y0 + wy, 0), H - 1);
            int gx = min(max(x0 + wx, 0), W - 1);
            swin[i] = dbase[(size_t)gy * W + gx];
        }
    }
    bar_sync_128(barId);

    if (gl < 96) {
        int cy = gl >> 3;
        int h = gl & 7;
        int cyc = (cy < SSN) ? cy : 0;

        float acc[SSN];
        #pragma unroll
        for (int c = 0; c < SSN; c++) acc[c] = 0.0f;

        #pragma unroll 1
        for (int rr = 0; rr < 2; rr++) {
            int yy = 2 * h + rr;
            const float* wr = swin + (cyc + yy) * WINSZ;
            const float4* t4 = (const float4*)(stile + yy * TSZ);
            #pragma unroll 1
            for (int half = 0; half < 2; half++) {
                float wreg[18];
                const float* wh = wr + 8 * half;
                #pragma unroll
                for (int k = 0; k < 18; k++) wreg[k] = wh[k];
                float treg[8];
                float4 v0 = t4[2 * half], v1 = t4[2 * half + 1];
                treg[0] = v0.x; treg[1] = v0.y; treg[2] = v0.z; treg[3] = v0.w;
                treg[4] = v1.x; treg[5] = v1.y; treg[6] = v1.z; treg[7] = v1.w;
                #pragma unroll
                for (int cx = 0; cx < SSN; cx++) {
                    #pragma unroll
                    for (int j = 0; j < 8; j++) {
                        float d = wreg[cx + j] - treg[j];
                        acc[cx] = fmaf(d, d, acc[cx]);
                    }
                }
            }
        }
        #pragma unroll
        for (int c = 0; c < SSN; c++) {
            acc[c] += __shfl_down_sync(0xFFFFFFFFu, acc[c], 4);
            acc[c] += __shfl_down_sync(0xFFFFFFFFu, acc[c], 2);
            acc[c] += __shfl_down_sync(0xFFFFFFFFu, acc[c], 1);
        }
        if (h == 0 && cy < SSN) {
            float ay = (float)(cy - (SRR + PD)) / (float)SSN;
            #pragma unroll
            for (int cx = 0; cx < SSN; cx++) {
                float ax = (float)(cx - (SRR + PD)) / (float)SSN;
                sdist[cy * SSN + cx] = acc[cx] * (1.0f / 256.0f) + 0.1f * (ay * ay + ax * ax);
            }
        }
    }
    bar_sync_128(barId);

    // argmin partials (first-occurrence tie-break via index in low bits)
    unsigned long long key = 0xFFFFFFFFFFFFFFFFull;
    if (gl < 81) {
        int py = gl / 9, px = gl - py * 9;
        float v = sdist[(py + 1) * SSN + (px + 1)];
        key = ((unsigned long long)__float_as_uint(v) << 32) | (unsigned)gl;
    }
    if (gl < 96) {
        #pragma unroll
        for (int o = 16; o >= 1; o >>= 1)
            key = u64min(key, __shfl_down_sync(0xFFFFFFFFu, key, o));
        if ((gl & 31) == 0) spart[gl >> 5] = key;
    }
    bar_sync_128(barId);

    // every thread combines + refines redundantly (no publish barrier)
    key = u64min(u64min(spart[0], spart[1]), spart[2]);
    refine_calc(sdist, inity, initx, key, offy, offx, best);
}

// Fused two-level match: one CTA = one parent tile + its 4 child tiles.
// min 3 CTAs/SM: caps regs at ~42 (feasible after the half-row SSD restructure)
// to lift occupancy from 2 to 3 CTAs/SM.
__global__ void __launch_bounds__(512, 3) match2_kernel(
    const float* __restrict__ srcP, const float* __restrict__ dstP, int Hp, int Wp,
    const float* __restrict__ srcC, const float* __restrict__ dstC, int Hc, int Wc,
    const float* __restrict__ grandOff, int ntwg,
    float* __restrict__ outChildOff, int ntwc,
    float* __restrict__ outPixOff, float* __restrict__ outPixDist)
{
    __shared__ float s_win[4][WINAREA];
    __shared__ __align__(16) float s_tile[4][TSZ * TSZ];
    __shared__ __align__(16) float s_ptile[TSZ * TSZ];
    __shared__ float s_dist[4][SSN * SSN];
    __shared__ float s_pdist[SSN * SSN];
    __shared__ unsigned long long s_part[4][3];
    __shared__ unsigned long long s_ppart[3];

    int tx = blockIdx.x, ty = blockIdx.y, n = blockIdx.z;
    int tid = threadIdx.x;
    const float* sPb = srcP + (size_t)n * Hp * Wp;
    const float* dPb = dstP + (size_t)n * Hp * Wp;
    const float* sCb = srcC + (size_t)n * Hc * Wc;
    const float* dCb = dstC + (size_t)n * Hc * Wc;

    // parent init offset: broadcast read, computed per-thread
    float inity = 0.0f, initx = 0.0f;
    if (grandOff) {
        const float* p = &grandOff[(((size_t)n * ntwg + (ty >> 1)) * ntwg + (tx >> 1)) * 2];
        float o0 = 2.0f * p[0], o1 = 2.0f * p[1];
        float fy = (float)(ty * TSZ), fx = (float)(tx * TSZ);
        inity = rintf(fminf(fmaxf(o0 + fy, 0.0f), (float)(Hp - TSZ)) - fy);
        initx = rintf(fminf(fmaxf(o1 + fx, 0.0f), (float)(Wp - TSZ)) - fx);
    }

    // ---- stage 0: all loads in parallel ----
    {
        int y0 = ty * TSZ + (int)inity - (SRR + PD);
        int x0 = tx * TSZ + (int)initx - (SRR + PD);
        if (y0 >= 0 && y0 + WINSZ <= Hp && x0 >= 0 && x0 + WINSZ <= Wp) {
            const float* base = dPb + (size_t)y0 * Wp + x0;
            for (int i = tid; i < WINAREA; i += 512) {
                int wy = i / WINSZ, wx = i - wy * WINSZ;
                s_win[0][i] = base[(size_t)wy * Wp + wx];
            }
        } else {
            for (int i = tid; i < WINAREA; i += 512) {
                int wy = i / WINSZ, wx = i - wy * WINSZ;
                int gy = min(max(y0 + wy, 0), Hp - 1);
                int gx = min(max(x0 + wx, 0), Wp - 1);
                s_win[0][i] = dPb[(size_t)gy * Wp + gx];
            }
        }
        if (tid < 256) {
            int yy = tid >> 4, xx = tid & 15;
            s_ptile[tid] = sPb[(size_t)(ty * TSZ + yy) * Wp + tx * TSZ + xx];
        }
        for (int i = tid; i < 4 * TSZ * TSZ; i += 512) {
            int child = i >> 8;
            int j = i & 255;
            int yy = j >> 4, xx = j & 15;
            int cty = 2 * ty + (child >> 1), ctx = 2 * tx + (child & 1);
            s_tile[child][j] = sCb[(size_t)(cty * TSZ + yy) * Wc + ctx * TSZ + xx];
        }
    }
    __syncthreads();

    // ---- stage 1: parent SSD across all 512 threads; warp w = candidate row cy ----
    {
        int cyp = tid >> 5;
        int h = tid & 31;
        if (cyp < SSN) {
            int row = h >> 1, half = h & 1;
            const float* wr = s_win[0] + (cyp + row) * WINSZ + half * 8;
            float wreg[18];
            #pragma unroll
            for (int k = 0; k < 18; k++) wreg[k] = wr[k];
            float treg[8];
            const float4* t4 = (const float4*)(s_ptile + row * TSZ + half * 8);
            float4 v0 = t4[0], v1 = t4[1];
            treg[0] = v0.x; treg[1] = v0.y; treg[2] = v0.z; treg[3] = v0.w;
            treg[4] = v1.x; treg[5] = v1.y; treg[6] = v1.z; treg[7] = v1.w;

            float acc[SSN];
            #pragma unroll
            for (int c = 0; c < SSN; c++) acc[c] = 0.0f;
            #pragma unroll
            for (int cx = 0; cx < SSN; cx++) {
                #pragma unroll
                for (int j = 0; j < 8; j++) {
                    float d = wreg[cx + j] - treg[j];
                    acc[cx] = fmaf(d, d, acc[cx]);
                }
            }
            #pragma unroll
            for (int c = 0; c < SSN; c++) {
                acc[c] += __shfl_down_sync(0xFFFFFFFFu, acc[c], 16);
                acc[c] += __shfl_down_sync(0xFFFFFFFFu, acc[c], 8);
                acc[c] += __shfl_down_sync(0xFFFFFFFFu, acc[c], 4);
                acc[c] += __shfl_down_sync(0xFFFFFFFFu, acc[c], 2);
                acc[c] += __shfl_down_sync(0xFFFFFFFFu, acc[c], 1);
            }
            if (h == 0) {
                float ay = (float)(cyp - (SRR + PD)) / (float)SSN;
                #pragma unroll
                for (int cx = 0; cx < SSN; cx++) {
                    float ax = (float)(cx - (SRR + PD)) / (float)SSN;
                    s_pdist[cyp * SSN + cx] = acc[cx] * (1.0f / 256.0f) + 0.1f * (ay * ay + ax * ax);
                }
            }
        }
    }
    __syncthreads();

    // parent argmin partials
    {
        unsigned long long key = 0xFFFFFFFFFFFFFFFFull;
        if (tid < 81) {
            int py = tid / 9, px = tid - py * 9;
            float v = s_pdist[(py + 1) * SSN + (px + 1)];
            key = ((unsigned long long)__float_as_uint(v) << 32) | (unsigned)tid;
        }
        if (tid < 96) {
            #pragma unroll
            for (int o = 16; o >= 1; o >>= 1)
                key = u64min(key, __shfl_down_sync(0xFFFFFFFFu, key, o));
            if ((tid & 31) == 0) s_ppart[tid >> 5] = key;
        }
    }
    __syncthreads();

    // all threads combine + refine parent redundantly (no publish barrier)
    float poy, pox, pbest;
    {
        unsigned long long key = u64min(u64min(s_ppart[0], s_ppart[1]), s_ppart[2]);
        refine_calc(s_pdist, inity, initx, key, poy, pox, pbest);
    }

    // ---- stage 2: 4 children in parallel ----
    int group = tid >> 7, gl = tid & 127;
    int cty = 2 * ty + (group >> 1), ctx = 2 * tx + (group & 1);
    float o0 = 2.0f * poy, o1 = 2.0f * pox;
    float fy = (float)(cty * TSZ), fx = (float)(ctx * TSZ);
    float ciy = rintf(fminf(fmaxf(o0 + fy, 0.0f), (float)(Hc - TSZ)) - fy);
    float cix = rintf(fminf(fmaxf(o1 + fx, 0.0f), (float)(Wc - TSZ)) - fx);

    float offy, offx, mind;
    tile_match_child(cty, ctx, ciy, cix, dCb, Hc, Wc,
                     gl, /*barId=*/1 + group, s_win[group], s_tile[group], s_dist[group],
                     s_part[group], offy, offx, mind);

    if (outChildOff) {
        if (gl == 0) {
            float* o = &outChildOff[(((size_t)n * ntwc + cty) * ntwc + ctx) * 2];
            o[0] = offy; o[1] = offx;
        }
    }
    if (outPixOff) {
        float2* po = (float2*)outPixOff;
        float2 ov = make_float2(offy, offx);
        for (int i = gl; i < TSZ * TSZ; i += 128) {
            int yy = i >> 4, xx = i & 15;
            size_t pidx = ((size_t)n * Hc + cty * TSZ + yy) * Wc + ctx * TSZ + xx;
            po[pidx] = ov;
            outPixDist[pidx] = mind;
        }
    }
}

extern "C" void kernel_launch(void* const* d_in, const int* in_sizes, int n_in,
                              void* d_out, int out_size) {
    (void)in_sizes; (void)n_in; (void)out_size;
    const float* src = (const float*)d_in[0];
    const float* dst = (const float*)d_in[1];

    float *ps1, *ps2, *ps3, *pd1, *pd2, *pd3, *off2;
    cudaGetSymbolAddress((void**)&ps1, g_ps1);
    cudaGetSymbolAddress((void**)&ps2, g_ps2);
    cudaGetSymbolAddress((void**)&ps3, g_ps3);
    cudaGetSymbolAddress((void**)&pd1, g_pd1);
    cudaGetSymbolAddress((void**)&pd2, g_pd2);
    cudaGetSymbolAddress((void**)&pd3, g_pd3);
    cudaGetSymbolAddress((void**)&off2, g_off2);

    float* outPixOff = (float*)d_out;                              // (4,512,512,2)
    float* outPixDist = (float*)d_out + (size_t)4 * 512 * 512 * 2; // (4,512,512)

    blur_all_kernel<<<dim3(8, 8, 8), 256>>>(src, dst, ps1, pd1, ps2, pd2, ps3, pd3);

    match2_kernel<<<dim3(4, 4, 4), 512>>>(ps3, pd3, 64, 64, ps2, pd2, 128, 128,
                                          nullptr, 0, off2, 8, nullptr, nullptr);
    match2_kernel<<<dim3(16, 16, 4), 512>>>(ps1, pd1, 256, 256, src, dst, 512, 512,
                                            off2, 8, nullptr, 0, outPixOff, outPixDist);
}